// round 10
// baseline (speedup 1.0000x reference)
#include <cuda_runtime.h>
#include <cuda_bf16.h>
#include <cstdint>

// Problem dims (fixed): B=64, T=1024, I=H=256, G=4H=1024
// ---------------- device scratch (static; no runtime allocations) ----------------
__device__ float         g_Wq[1024 * 256];              // quantized w_ih (fp32, exact grid values)
__device__ __nv_bfloat16 g_Whh[1024 * 256];             // quantized w_hh (exact in bf16)
__device__ float         g_bias[1024];                  // fq(b_ih)+fq(b_hh)
__device__ float         g_xs[(size_t)65536 * 1024];    // [t*64+b][g] input projections (+bias)

// ---------------- helpers ----------------
__device__ __forceinline__ float fq(float x) {
    // round-half-even to 1/16 grid, clamp (matches jnp.round + clip; all ops exact)
    float q = __fmul_rn(rintf(__fmul_rn(x, 16.0f)), 0.0625f);
    return fminf(fmaxf(q, -8.0f), 7.9375f);
}

// XLA EmitTanh: Cephes rational, FMA-contracted Horner, clamp 7.99881172180175781.
__device__ __forceinline__ float tanh_ref(float x) {
    float ax = fabsf(x);
    float xc = fminf(fmaxf(x, -7.99881172180175781f), 7.99881172180175781f);
    float x2 = __fmul_rn(xc, xc);
    float p = -2.76076847742355e-16f;
    p = __fmaf_rn(x2, p, 2.00018790482477e-13f);
    p = __fmaf_rn(x2, p, -8.60467152213735e-11f);
    p = __fmaf_rn(x2, p, 5.12229709037114e-08f);
    p = __fmaf_rn(x2, p, 1.48572235717979e-05f);
    p = __fmaf_rn(x2, p, 6.37261928875436e-04f);
    p = __fmaf_rn(x2, p, 4.89352455891786e-03f);
    float num = __fmul_rn(xc, p);
    float den = 1.19825839466702e-06f;
    den = __fmaf_rn(x2, den, 1.18534705686654e-04f);
    den = __fmaf_rn(x2, den, 2.26843463243900e-03f);
    den = __fmaf_rn(x2, den, 4.89352518554385e-03f);
    float r = __fdiv_rn(num, den);
    return (ax < 0.0004f) ? x : r;
}

// Faithfully-rounded float exp (Juffa algorithm); immune to --use_fast_math.
__device__ __forceinline__ float expf_acc(float a) {
    float f, r, j, s, t;
    int i, ia;
    j = __fmaf_rn(1.442695f, a, 12582912.f);     // log2(e), round-to-int shifter
    j = __fadd_rn(j, -12582912.f);               // 0x1.8p23
    f = __fmaf_rn(j, -6.93145752e-1f, a);        // -ln2_hi
    f = __fmaf_rn(j, -1.42860677e-6f, f);        // -ln2_lo
    i = (int)j;
    r = 1.37805939e-3f;
    r = __fmaf_rn(r, f, 8.37312452e-3f);
    r = __fmaf_rn(r, f, 4.16695364e-2f);
    r = __fmaf_rn(r, f, 1.66664720e-1f);
    r = __fmaf_rn(r, f, 4.99999851e-1f);
    r = __fmaf_rn(r, f, 1.00000000e+0f);
    r = __fmaf_rn(r, f, 1.00000000e+0f);
    ia = (i > 0) ? 0 : 0x83000000;
    s = __int_as_float(0x7f000000 + ia);
    t = __int_as_float((i << 23) - ia);
    r = __fmul_rn(__fmul_rn(r, s), t);
    if (fabsf(a) >= 104.0f) r = __fmul_rn(s, s); // over/underflow
    return r;
}

// XLA LogisticExpander: logistic(x) = 1 / (1 + exp(-x)), IEEE division.
__device__ __forceinline__ float sigmoid_ref(float x) {
    float e = expf_acc(-x);
    return __fdiv_rn(1.0f, __fadd_rn(1.0f, e));
}

// ---------------- prep kernel ----------------
__global__ void k_prep_w(const float* __restrict__ wih, const float* __restrict__ whh,
                         const float* __restrict__ bih, const float* __restrict__ bhh) {
    int g = blockIdx.x;          // 0..1023
    int k = threadIdx.x;         // 0..255
    g_Wq[g * 256 + k] = fq(wih[g * 256 + k]);
    g_Whh[g * 256 + k] = __float2bfloat16(fq(whh[g * 256 + k]));   // exact (j/16, small ints)
    if (k == 0) g_bias[g] = __fadd_rn(fq(bih[g]), fq(bhh[g]));
}

// ---------------- input projection: exact sequential-chain SGEMM ----------------
// xs[m][g] = single fp32 FMA chain over ascending k (Eigen gebp per-element order), + bias.
// Tiling: 128m x 128g per CTA, 256 threads, thread tile 8m x 8g (f32x2 pairs along g).
__global__ void __launch_bounds__(256) k_gemm_chain(const float* __restrict__ x) {
    __shared__ float Xs[32][132];   // [k][m]
    __shared__ float Ws[32][132];   // [k][g interleaved: idx = (g&7)*16 + (g>>3)]
    const int tid = threadIdx.x;
    const int m0 = blockIdx.y * 128, n0 = blockIdx.x * 128;
    const int tm = tid >> 4;   // 0..15 -> m = tm*8..
    const int tn = tid & 15;   // 0..15 -> g = tn*8..

    float bias0[8];
#pragma unroll
    for (int j = 0; j < 8; j++) bias0[j] = g_bias[n0 + tn * 8 + j];

    unsigned long long acc[8][4];
#pragma unroll
    for (int i = 0; i < 8; i++)
#pragma unroll
        for (int j = 0; j < 4; j++) acc[i][j] = 0ull;

    for (int kc = 0; kc < 256; kc += 32) {
        __syncthreads();
#pragma unroll
        for (int j = 0; j < 4; j++) {
            int f4 = tid + 256 * j;            // 0..1023
            int mr = f4 >> 3;                  // 0..127
            int kq = (f4 & 7) * 4;             // 0,4,..,28
            float4 xv = *(const float4*)(x + (size_t)(m0 + mr) * 256 + kc + kq);
            Xs[kq + 0][mr] = xv.x;
            Xs[kq + 1][mr] = xv.y;
            Xs[kq + 2][mr] = xv.z;
            Xs[kq + 3][mr] = xv.w;
            float4 wv = *(const float4*)(g_Wq + (size_t)(n0 + mr) * 256 + kc + kq);
            int gt = (mr & 7) * 16 + (mr >> 3);
            Ws[kq + 0][gt] = wv.x;
            Ws[kq + 1][gt] = wv.y;
            Ws[kq + 2][gt] = wv.z;
            Ws[kq + 3][gt] = wv.w;
        }
        __syncthreads();
#pragma unroll 4
        for (int k = 0; k < 32; k++) {
            unsigned long long a2[8];
#pragma unroll
            for (int i = 0; i < 8; i++) {
                float a = Xs[k][tm * 8 + i];
                asm("mov.b64 %0, {%1, %1};" : "=l"(a2[i]) : "f"(a));
            }
            unsigned long long b2[4];
#pragma unroll
            for (int jp = 0; jp < 4; jp++) {
                float w0 = Ws[k][(2 * jp) * 16 + tn];
                float w1 = Ws[k][(2 * jp + 1) * 16 + tn];
                asm("mov.b64 %0, {%1, %2};" : "=l"(b2[jp]) : "f"(w0), "f"(w1));
            }
#pragma unroll
            for (int i = 0; i < 8; i++)
#pragma unroll
                for (int jp = 0; jp < 4; jp++)
                    asm("fma.rn.f32x2 %0, %1, %2, %0;" : "+l"(acc[i][jp]) : "l"(a2[i]), "l"(b2[jp]));
        }
    }

    // epilogue: +bias (single fadd), scatter row m=(b*1024+t) -> (t*64+b)
#pragma unroll
    for (int i = 0; i < 8; i++) {
        int m = m0 + tm * 8 + i;
        int row = (m & 1023) * 64 + (m >> 10);
        float v[8];
#pragma unroll
        for (int jp = 0; jp < 4; jp++) {
            float lo, hi;
            asm("mov.b64 {%0, %1}, %2;" : "=f"(lo), "=f"(hi) : "l"(acc[i][jp]));
            v[2 * jp]     = __fadd_rn(lo, bias0[2 * jp]);
            v[2 * jp + 1] = __fadd_rn(hi, bias0[2 * jp + 1]);
        }
        float4* dst = (float4*)(g_xs + (size_t)row * 1024 + n0 + tn * 8);
        dst[0] = make_float4(v[0], v[1], v[2], v[3]);
        dst[1] = make_float4(v[4], v[5], v[6], v[7]);
    }
}

// ---------------- recurrence: 16 independent clusters of 8 CTAs ----------------
// Recurrent matmul is EXACT in fp32 (1/256 grid, integer numerators < 2^22) ->
// order-free, bitwise equal to any reference accumulation.
#define SM_HS 65536
#define SM_GS 69632
#define SM_TOT 71680

__global__ void __launch_bounds__(128) __cluster_dims__(8, 1, 1)
k_recur(float* __restrict__ out) {
    extern __shared__ char smem[];
    uint32_t* w2s = (uint32_t*)smem;
    float*    gs  = (float*)(smem + SM_GS);

    const int tid   = threadIdx.x;
    const int rank  = blockIdx.x & 7;
    const int gbase = rank * 128;
    const int bbase = (blockIdx.x >> 3) * 4;

    uint32_t sb;
    asm("{ .reg .u64 t0; cvta.to.shared.u64 t0, %1; cvt.u32.u64 %0, t0; }"
        : "=r"(sb) : "l"(smem));
    const uint32_t hs_sb = sb + SM_HS;

    // load w_hh slice, packed: w2s[k2][g] = (w[g][2k2], w[g][2k2+1]) as bf16x2
    const uint32_t* wrow = (const uint32_t*)g_Whh + (size_t)(gbase + tid) * 128;
#pragma unroll 8
    for (int k2 = 0; k2 < 128; k2++) w2s[k2 * 128 + tid] = wrow[k2];
    // zero h state
    float* hsf = (float*)(smem + SM_HS);
    for (int i = tid; i < 1024; i += 128) hsf[i] = 0.0f;
    __syncthreads();

    // precompute remote gate-slot address (fixed all steps)
    const int ggl = gbase + tid;
    const int gate_idx = ggl >> 8;
    const int hidx = ggl & 255;
    uint32_t gloc = sb + SM_GS + (uint32_t)(((gate_idx * 4) * 32 + (hidx & 31)) * 4);
    uint32_t graddr;
    asm("mapa.shared::cluster.u32 %0, %1, %2;" : "=r"(graddr) : "r"(gloc), "r"(hidx >> 5));

    // elementwise identity + h-broadcast addresses
    const int b_ew = tid >> 5, hl = tid & 31;
    const int hg = rank * 32 + hl;
    uint32_t hloc = hs_sb + (uint32_t)((hg * 4 + b_ew) * 4);
    uint32_t haddr[8];
#pragma unroll
    for (int r = 0; r < 8; r++)
        asm("mapa.shared::cluster.u32 %0, %1, %2;" : "=r"(haddr[r]) : "r"(hloc), "r"(r));

    float c = 0.0f;

    asm volatile("barrier.cluster.arrive.aligned;\n\tbarrier.cluster.wait.aligned;" ::: "memory");

    const float* xsp = g_xs + (size_t)bbase * 1024 + ggl;

    for (int t = 0; t < 1024; t++) {
        const float* xt = xsp + (size_t)t * 65536;
        float x0 = xt[0], x1 = xt[1024], x2 = xt[2048], x3 = xt[3072];

        // gates[g][b0..b3] = sum_k h_q[b][k] * w[g][k]   (exact, order-free)
        unsigned long long a01a = 0ull, a01b = 0ull, a23a = 0ull, a23b = 0ull;
        uint32_t hrow = hs_sb;
#pragma unroll 4
        for (int k2 = 0; k2 < 128; k2++) {
            uint32_t u = w2s[k2 * 128 + tid];
            uint32_t wlo = u << 16, whi = u & 0xffff0000u;
            unsigned long long wl2, wh2, hA01, hA23, hB01, hB23;
            asm("mov.b64 %0, {%1, %1};" : "=l"(wl2) : "r"(wlo));
            asm("mov.b64 %0, {%1, %1};" : "=l"(wh2) : "r"(whi));
            asm("ld.shared.v2.u64 {%0, %1}, [%2];" : "=l"(hA01), "=l"(hA23) : "r"(hrow));
            asm("ld.shared.v2.u64 {%0, %1}, [%2];" : "=l"(hB01), "=l"(hB23) : "r"(hrow + 16));
            asm("fma.rn.f32x2 %0, %1, %2, %0;" : "+l"(a01a) : "l"(hA01), "l"(wl2));
            asm("fma.rn.f32x2 %0, %1, %2, %0;" : "+l"(a23a) : "l"(hA23), "l"(wl2));
            asm("fma.rn.f32x2 %0, %1, %2, %0;" : "+l"(a01b) : "l"(hB01), "l"(wh2));
            asm("fma.rn.f32x2 %0, %1, %2, %0;" : "+l"(a23b) : "l"(hB23), "l"(wh2));
            hrow += 32;
        }
        unsigned long long acc01, acc23;
        asm("add.rn.f32x2 %0, %1, %2;" : "=l"(acc01) : "l"(a01a), "l"(a01b));
        asm("add.rn.f32x2 %0, %1, %2;" : "=l"(acc23) : "l"(a23a), "l"(a23b));
        float p0, p1, p2, p3;
        asm("mov.b64 {%0, %1}, %2;" : "=f"(p0), "=f"(p1) : "l"(acc01));
        asm("mov.b64 {%0, %1}, %2;" : "=f"(p2), "=f"(p3) : "l"(acc23));
        p0 = __fadd_rn(p0, x0); p1 = __fadd_rn(p1, x1);
        p2 = __fadd_rn(p2, x2); p3 = __fadd_rn(p3, x3);

        // deliver gates directly into the owning CTA's smem
        asm volatile("st.shared::cluster.b32 [%0], %1;" :: "r"(graddr),       "r"(__float_as_uint(p0)) : "memory");
        asm volatile("st.shared::cluster.b32 [%0], %1;" :: "r"(graddr + 128), "r"(__float_as_uint(p1)) : "memory");
        asm volatile("st.shared::cluster.b32 [%0], %1;" :: "r"(graddr + 256), "r"(__float_as_uint(p2)) : "memory");
        asm volatile("st.shared::cluster.b32 [%0], %1;" :: "r"(graddr + 384), "r"(__float_as_uint(p3)) : "memory");

        asm volatile("barrier.cluster.arrive.aligned;\n\tbarrier.cluster.wait.aligned;" ::: "memory");

        // elementwise LSTM cell — XLA lowering:
        //   sigmoid = 1/(1+exp(-x))   (LogisticExpander)
        //   tanh    = Cephes rational (EmitTanh, FMA form)
        float gi = gs[(0 * 4 + b_ew) * 32 + hl];
        float gf = gs[(1 * 4 + b_ew) * 32 + hl];
        float gg = gs[(2 * 4 + b_ew) * 32 + hl];
        float go = gs[(3 * 4 + b_ew) * 32 + hl];
        float vi = sigmoid_ref(gi);
        float vf = sigmoid_ref(gf);
        float vg = tanh_ref(gg);
        float vo = sigmoid_ref(go);
        float cq = fq(c);
        // c1 = f*c_q + i*g -> backend contraction: fma(f, cq, mul(i, g))
        c = __fmaf_rn(vf, cq, __fmul_rn(vi, vg));
        float h1 = __fmul_rn(vo, tanh_ref(c));

        out[((size_t)(bbase + b_ew) * 1024 + t) * 256 + hg] = h1;
        if (t == 1023) {
            size_t o = (size_t)16777216 + (size_t)(bbase + b_ew) * 256 + hg;
            out[o] = h1;          // hT
            out[o + 16384] = c;   // cT
        }

        // broadcast quantized h to all 8 CTAs' h state
        uint32_t hqb = __float_as_uint(fq(h1));
#pragma unroll
        for (int r = 0; r < 8; r++)
            asm volatile("st.shared::cluster.b32 [%0], %1;" :: "r"(haddr[r]), "r"(hqb) : "memory");

        asm volatile("barrier.cluster.arrive.aligned;\n\tbarrier.cluster.wait.aligned;" ::: "memory");
    }
}

// ---------------- launch ----------------
extern "C" void kernel_launch(void* const* d_in, const int* in_sizes, int n_in,
                              void* d_out, int out_size) {
    const float* x   = (const float*)d_in[0];
    const float* wih = (const float*)d_in[1];
    const float* whh = (const float*)d_in[2];
    const float* bih = (const float*)d_in[3];
    const float* bhh = (const float*)d_in[4];
    float* out = (float*)d_out;

    cudaFuncSetAttribute(k_recur, cudaFuncAttributeMaxDynamicSharedMemorySize, SM_TOT);

    k_prep_w<<<1024, 256>>>(wih, whh, bih, bhh);
    k_gemm_chain<<<dim3(8, 512), 256>>>(x);
    k_recur<<<128, 128, SM_TOT>>>(out);
}

// round 11
// speedup vs baseline: 2.6866x; 2.6866x over previous
#include <cuda_runtime.h>
#include <cuda_bf16.h>
#include <cstdint>

// Problem dims (fixed): B=64, T=1024, I=H=256, G=4H=1024
// ---------------- device scratch (static; no runtime allocations) ----------------
__device__ float         g_Wq[1024 * 256];              // quantized w_ih (fp32, exact grid values)
__device__ __nv_bfloat16 g_Whh[1024 * 256];             // quantized w_hh (exact in bf16)
__device__ float         g_bias[1024];                  // fq(b_ih)+fq(b_hh)
__device__ float         g_xs[(size_t)65536 * 1024];    // [t*64+b][g] input projections (+bias)

// ---------------- helpers ----------------
__device__ __forceinline__ float fq(float x) {
    float q = __fmul_rn(rintf(__fmul_rn(x, 16.0f)), 0.0625f);
    return fminf(fmaxf(q, -8.0f), 7.9375f);
}

// XLA EmitTanh: Cephes rational, FMA-contracted Horner, clamp 7.99881172180175781.
__device__ __forceinline__ float tanh_ref(float x) {
    float ax = fabsf(x);
    float xc = fminf(fmaxf(x, -7.99881172180175781f), 7.99881172180175781f);
    float x2 = __fmul_rn(xc, xc);
    float p = -2.76076847742355e-16f;
    p = __fmaf_rn(x2, p, 2.00018790482477e-13f);
    p = __fmaf_rn(x2, p, -8.60467152213735e-11f);
    p = __fmaf_rn(x2, p, 5.12229709037114e-08f);
    p = __fmaf_rn(x2, p, 1.48572235717979e-05f);
    p = __fmaf_rn(x2, p, 6.37261928875436e-04f);
    p = __fmaf_rn(x2, p, 4.89352455891786e-03f);
    float num = __fmul_rn(xc, p);
    float den = 1.19825839466702e-06f;
    den = __fmaf_rn(x2, den, 1.18534705686654e-04f);
    den = __fmaf_rn(x2, den, 2.26843463243900e-03f);
    den = __fmaf_rn(x2, den, 4.89352518554385e-03f);
    float r = __fdiv_rn(num, den);
    return (ax < 0.0004f) ? x : r;
}

// Faithfully-rounded expf (Juffa); immune to --use_fast_math.
__device__ __forceinline__ float expf_acc(float a) {
    float f, r, j, s, t;
    int i, ia;
    j = __fmaf_rn(1.442695f, a, 12582912.f);
    j = __fadd_rn(j, -12582912.f);
    f = __fmaf_rn(j, -6.93145752e-1f, a);
    f = __fmaf_rn(j, -1.42860677e-6f, f);
    i = (int)j;
    r = 1.37805939e-3f;
    r = __fmaf_rn(r, f, 8.37312452e-3f);
    r = __fmaf_rn(r, f, 4.16695364e-2f);
    r = __fmaf_rn(r, f, 1.66664720e-1f);
    r = __fmaf_rn(r, f, 4.99999851e-1f);
    r = __fmaf_rn(r, f, 1.00000000e+0f);
    r = __fmaf_rn(r, f, 1.00000000e+0f);
    ia = (i > 0) ? 0 : 0x83000000;
    s = __int_as_float(0x7f000000 + ia);
    t = __int_as_float((i << 23) - ia);
    r = __fmul_rn(__fmul_rn(r, s), t);
    if (fabsf(a) >= 104.0f) r = __fmul_rn(s, s);
    return r;
}

// XLA LogisticExpander: logistic(x) = 1 / (1 + exp(-x)), IEEE division.
__device__ __forceinline__ float sigmoid_ref(float x) {
    float e = expf_acc(-x);
    return __fdiv_rn(1.0f, __fadd_rn(1.0f, e));
}

__device__ __forceinline__ void mma16816(float c[4], const uint32_t a[4], const uint32_t b[2]) {
    asm volatile(
        "mma.sync.aligned.m16n8k16.row.col.f32.bf16.bf16.f32 "
        "{%0,%1,%2,%3}, {%4,%5,%6,%7}, {%8,%9}, {%0,%1,%2,%3};\n"
        : "+f"(c[0]), "+f"(c[1]), "+f"(c[2]), "+f"(c[3])
        : "r"(a[0]), "r"(a[1]), "r"(a[2]), "r"(a[3]), "r"(b[0]), "r"(b[1]));
}

// ---------------- prep kernel ----------------
__global__ void k_prep_w(const float* __restrict__ wih, const float* __restrict__ whh,
                         const float* __restrict__ bih, const float* __restrict__ bhh) {
    int g = blockIdx.x;          // 0..1023
    int k = threadIdx.x;         // 0..255
    g_Wq[g * 256 + k] = fq(wih[g * 256 + k]);
    g_Whh[g * 256 + k] = __float2bfloat16(fq(whh[g * 256 + k]));   // exact (j/16, |j|<=128)
    if (k == 0) g_bias[g] = __fadd_rn(fq(bih[g]), fq(bhh[g]));
}

// ---------------- input projection: exact sequential-chain SGEMM (unchanged, bitwise) ----
__global__ void __launch_bounds__(256) k_gemm_chain(const float* __restrict__ x) {
    __shared__ float Xs[32][132];
    __shared__ float Ws[32][132];
    const int tid = threadIdx.x;
    const int m0 = blockIdx.y * 128, n0 = blockIdx.x * 128;
    const int tm = tid >> 4;
    const int tn = tid & 15;

    float bias0[8];
#pragma unroll
    for (int j = 0; j < 8; j++) bias0[j] = g_bias[n0 + tn * 8 + j];

    unsigned long long acc[8][4];
#pragma unroll
    for (int i = 0; i < 8; i++)
#pragma unroll
        for (int j = 0; j < 4; j++) acc[i][j] = 0ull;

    for (int kc = 0; kc < 256; kc += 32) {
        __syncthreads();
#pragma unroll
        for (int j = 0; j < 4; j++) {
            int f4 = tid + 256 * j;
            int mr = f4 >> 3;
            int kq = (f4 & 7) * 4;
            float4 xv = *(const float4*)(x + (size_t)(m0 + mr) * 256 + kc + kq);
            Xs[kq + 0][mr] = xv.x;
            Xs[kq + 1][mr] = xv.y;
            Xs[kq + 2][mr] = xv.z;
            Xs[kq + 3][mr] = xv.w;
            float4 wv = *(const float4*)(g_Wq + (size_t)(n0 + mr) * 256 + kc + kq);
            int gt = (mr & 7) * 16 + (mr >> 3);
            Ws[kq + 0][gt] = wv.x;
            Ws[kq + 1][gt] = wv.y;
            Ws[kq + 2][gt] = wv.z;
            Ws[kq + 3][gt] = wv.w;
        }
        __syncthreads();
#pragma unroll 4
        for (int k = 0; k < 32; k++) {
            unsigned long long a2[8];
#pragma unroll
            for (int i = 0; i < 8; i++) {
                float a = Xs[k][tm * 8 + i];
                asm("mov.b64 %0, {%1, %1};" : "=l"(a2[i]) : "f"(a));
            }
            unsigned long long b2[4];
#pragma unroll
            for (int jp = 0; jp < 4; jp++) {
                float w0 = Ws[k][(2 * jp) * 16 + tn];
                float w1 = Ws[k][(2 * jp + 1) * 16 + tn];
                asm("mov.b64 %0, {%1, %2};" : "=l"(b2[jp]) : "f"(w0), "f"(w1));
            }
#pragma unroll
            for (int i = 0; i < 8; i++)
#pragma unroll
                for (int jp = 0; jp < 4; jp++)
                    asm("fma.rn.f32x2 %0, %1, %2, %0;" : "+l"(acc[i][jp]) : "l"(a2[i]), "l"(b2[jp]));
        }
    }

#pragma unroll
    for (int i = 0; i < 8; i++) {
        int m = m0 + tm * 8 + i;
        int row = (m & 1023) * 64 + (m >> 10);
        float v[8];
#pragma unroll
        for (int jp = 0; jp < 4; jp++) {
            float lo, hi;
            asm("mov.b64 {%0, %1}, %2;" : "=f"(lo), "=f"(hi) : "l"(acc[i][jp]));
            v[2 * jp]     = __fadd_rn(lo, bias0[2 * jp]);
            v[2 * jp + 1] = __fadd_rn(hi, bias0[2 * jp + 1]);
        }
        float4* dst = (float4*)(g_xs + (size_t)row * 1024 + n0 + tn * 8);
        dst[0] = make_float4(v[0], v[1], v[2], v[3]);
        dst[1] = make_float4(v[4], v[5], v[6], v[7]);
    }
}

// ---------------- recurrence: HMMA + register-resident weights ----------------
// 16 clusters of 8 CTAs. CTA rank r owns h-slice hu in [32r, 32r+32) and computes
// EXACTLY the gate rows it needs: g = gate*256 + 32r + (0..31)  (gate = warp 0..3).
// Gates stay LOCAL (smem); only bf16 h_q is broadcast cluster-wide (double-buffered)
// -> ONE cluster barrier per step.
// HMMA m16n8k16 bf16->f32: operands on 1/16 integer grid -> accumulation EXACT,
// bitwise identical to the reference matmul.
__global__ void __launch_bounds__(128) __cluster_dims__(8, 1, 1)
k_recur(float* __restrict__ out) {
    __shared__ uint32_t hs2[2][128][8];   // [buf][k2][b] : bf16x2 (h[2k2], h[2k2+1]) per batch
    __shared__ float gs[128][9];          // [g_local][b]  (pad 9 -> conflict-free reads)

    const int tid  = threadIdx.x;
    const int lane = tid & 31, warp = tid >> 5;
    const int gid  = lane >> 2, tig = lane & 3;        // mma group id / thread-in-group
    const int rank  = blockIdx.x & 7;
    const int bbase = (blockIdx.x >> 3) * 4;

    // zero both h buffers (h0 = 0; cols b>=4 stay 0 forever)
    for (int i = tid; i < 2 * 128 * 8; i += 128) ((uint32_t*)hs2)[i] = 0u;

    // A fragments (w_hh) -> registers, loaded once. Rows: g0 .. g0+31 (this warp's gate).
    uint32_t afr[2][16][4];
    const uint32_t* W = (const uint32_t*)g_Whh;        // [g][k2] bf16x2
    const int g0 = warp * 256 + rank * 32;
#pragma unroll
    for (int mt = 0; mt < 2; mt++)
#pragma unroll
        for (int kt = 0; kt < 16; kt++) {
            int r = g0 + mt * 16 + gid;
            int cc = kt * 8 + tig;
            afr[mt][kt][0] = W[r * 128 + cc];
            afr[mt][kt][1] = W[(r + 8) * 128 + cc];
            afr[mt][kt][2] = W[r * 128 + cc + 4];
            afr[mt][kt][3] = W[(r + 8) * 128 + cc + 4];
        }

    // elementwise identity: thread = (batch b_ew, hidden unit hu)
    const int b_ew = warp, hl = lane;
    const int hu = rank * 32 + hl;

    // remote h-slot addresses (buffer 0; buffer stride = 4096 B)
    uint32_t hloc;
    asm("{ .reg .u64 t0; cvta.to.shared.u64 t0, %1; cvt.u32.u64 %0, t0; }"
        : "=r"(hloc) : "l"(&hs2[0][hu >> 1][b_ew]));
    uint32_t haddr[8];
#pragma unroll
    for (int r = 0; r < 8; r++)
        asm("mapa.shared::cluster.u32 %0, %1, %2;" : "=r"(haddr[r]) : "r"(hloc), "r"(r));

    float c = 0.0f;

    __syncthreads();
    asm volatile("barrier.cluster.arrive.aligned;\n\tbarrier.cluster.wait.aligned;" ::: "memory");

    for (int t = 0; t < 1024; t++) {
        const int buf = t & 1;

        // prefetch xs for this thread's (b, hu): 4 gate columns
        const float* xt = g_xs + ((size_t)(t * 64 + bbase + b_ew)) * 1024 + hu;
        float x0 = xt[0], x1 = xt[256], x2 = xt[512], x3 = xt[768];

        // HMMA: gates[g_local 0..31 of this gate][b] over k=256 (16 k-tiles)
        float c0[4] = {0.f, 0.f, 0.f, 0.f}, c1[4] = {0.f, 0.f, 0.f, 0.f};
#pragma unroll
        for (int kt = 0; kt < 16; kt++) {
            uint32_t bfr[2];
            bfr[0] = hs2[buf][kt * 8 + tig][gid];
            bfr[1] = hs2[buf][kt * 8 + tig + 4][gid];
            mma16816(c0, afr[0][kt], bfr);
            mma16816(c1, afr[1][kt], bfr);
        }
        // C layout: c[0..1]=C[gid][2tig..2tig+1], c[2..3]=C[gid+8][...]; cols 0..3 = batches
        if (tig < 2) {
            int rb = warp * 32 + gid;
            gs[rb][2 * tig]          = c0[0];
            gs[rb][2 * tig + 1]      = c0[1];
            gs[rb + 8][2 * tig]      = c0[2];
            gs[rb + 8][2 * tig + 1]  = c0[3];
            gs[rb + 16][2 * tig]     = c1[0];
            gs[rb + 16][2 * tig + 1] = c1[1];
            gs[rb + 24][2 * tig]     = c1[2];
            gs[rb + 24][2 * tig + 1] = c1[3];
        }
        __syncthreads();

        // elementwise LSTM cell (bitwise-matched lowering, identical to R10)
        float gi = __fadd_rn(gs[hl][b_ew],      x0);
        float gf = __fadd_rn(gs[32 + hl][b_ew], x1);
        float gg = __fadd_rn(gs[64 + hl][b_ew], x2);
        float go = __fadd_rn(gs[96 + hl][b_ew], x3);
        float vi = sigmoid_ref(gi);
        float vf = sigmoid_ref(gf);
        float vg = tanh_ref(gg);
        float vo = sigmoid_ref(go);
        float cq = fq(c);
        c = __fmaf_rn(vf, cq, __fmul_rn(vi, vg));
        float h1 = __fmul_rn(vo, tanh_ref(c));

        out[((size_t)(bbase + b_ew) * 1024 + t) * 256 + hu] = h1;
        if (t == 1023) {
            size_t o = (size_t)16777216 + (size_t)(bbase + b_ew) * 256 + hu;
            out[o] = h1;          // hT
            out[o + 16384] = c;   // cT
        }

        // broadcast quantized h (exact in bf16) into NEXT buffer of all 8 CTAs
        uint16_t hb = (uint16_t)__bfloat16_as_ushort(__float2bfloat16(fq(h1)));
        uint32_t other = __shfl_xor_sync(0xffffffffu, (uint32_t)hb, 1);
        if ((hl & 1) == 0) {
            uint32_t packed = (uint32_t)hb | (other << 16);
            uint32_t off = (uint32_t)((buf ^ 1) * 4096);
#pragma unroll
            for (int r = 0; r < 8; r++)
                asm volatile("st.shared::cluster.b32 [%0], %1;"
                             :: "r"(haddr[r] + off), "r"(packed) : "memory");
        }

        asm volatile("barrier.cluster.arrive.aligned;\n\tbarrier.cluster.wait.aligned;" ::: "memory");
    }
}

// ---------------- launch ----------------
extern "C" void kernel_launch(void* const* d_in, const int* in_sizes, int n_in,
                              void* d_out, int out_size) {
    const float* x   = (const float*)d_in[0];
    const float* wih = (const float*)d_in[1];
    const float* whh = (const float*)d_in[2];
    const float* bih = (const float*)d_in[3];
    const float* bhh = (const float*)d_in[4];
    float* out = (float*)d_out;

    k_prep_w<<<1024, 256>>>(wih, whh, bih, bhh);
    k_gemm_chain<<<dim3(8, 512), 256>>>(x);
    k_recur<<<128, 128>>>(out);
}